// round 5
// baseline (speedup 1.0000x reference)
#include <cuda_runtime.h>
#include <math.h>

#define L_   4
#define D_   512
#define H_   8
#define HD_  64
#define DFF_ 2048
#define B_   8
#define S_   1024
#define BS_  (B_*S_)   // 8192 rows

// ---------------- scratch (device globals; no allocations allowed) ----------
__device__ float g_x [BS_*D_];    // residual stream
__device__ float g_h [BS_*D_];    // layernorm out / attention out
__device__ float g_q [BS_*D_];
__device__ float g_k [BS_*D_];
__device__ float g_v [BS_*D_];
__device__ float g_ff[BS_*DFF_];  // FFN hidden
__device__ int   g_len[B_];       // per-batch valid key count (prefix mask)

// ---------------- mask length extraction (mask is 4-byte 0/1, prefix) -------
__global__ __launch_bounds__(256) void masklen_kernel(const unsigned int* __restrict__ mask) {
    int b = blockIdx.x, t = threadIdx.x;
    int cnt = 0;
    for (int i = t; i < S_; i += 256) cnt += (mask[b * S_ + i] != 0u) ? 1 : 0;
    #pragma unroll
    for (int o = 16; o; o >>= 1) cnt += __shfl_xor_sync(0xffffffffu, cnt, o);
    __shared__ int sh[8];
    if ((t & 31) == 0) sh[t >> 5] = cnt;
    __syncthreads();
    if (t == 0) {
        int s = 0;
        #pragma unroll
        for (int w = 0; w < 8; w++) s += sh[w];
        g_len[b] = s;
    }
}

// ---------------- positional encoding + input copy --------------------------
__global__ __launch_bounds__(512) void posenc_kernel(const float* __restrict__ x) {
    int s = blockIdx.x, b = blockIdx.y, d = threadIdx.x;
    float j = (float)((d < 256) ? d : d - 256);
    float inv = powf(10000.0f, (2.0f * j) / 512.0f);
    float ang = (float)s / inv;
    float pe  = (d < 256) ? sinf(ang) : cosf(ang);
    size_t idx = ((size_t)b * S_ + s) * D_ + d;
    g_x[idx] = x[idx] + pe;
}

// ---------------- layernorm (one block per row, 128 thr x float4) -----------
__global__ __launch_bounds__(128) void ln_kernel(const float* __restrict__ in,
                                                 const float* __restrict__ gw,
                                                 const float* __restrict__ bw,
                                                 float* __restrict__ out) {
    int row = blockIdx.x;
    int t = threadIdx.x;
    const float4* rp = (const float4*)(in + (size_t)row * D_);
    float4 v = rp[t];
    float s  = v.x + v.y + v.z + v.w;
    float sq = v.x*v.x + v.y*v.y + v.z*v.z + v.w*v.w;
    #pragma unroll
    for (int o = 16; o; o >>= 1) {
        s  += __shfl_xor_sync(0xffffffffu, s,  o);
        sq += __shfl_xor_sync(0xffffffffu, sq, o);
    }
    __shared__ float sh[8];
    int wid = t >> 5, lane = t & 31;
    if (lane == 0) { sh[wid] = s; sh[4 + wid] = sq; }
    __syncthreads();
    s  = sh[0] + sh[1] + sh[2] + sh[3];
    sq = sh[4] + sh[5] + sh[6] + sh[7];
    float mu  = s * (1.0f / D_);
    float var = sq * (1.0f / D_) - mu * mu;
    float r   = rsqrtf(var + 1e-3f);
    float4 gg = ((const float4*)gw)[t];
    float4 bb = ((const float4*)bw)[t];
    float4 o4;
    o4.x = (v.x - mu) * r * gg.x + bb.x;
    o4.y = (v.y - mu) * r * gg.y + bb.y;
    o4.z = (v.z - mu) * r * gg.z + bb.z;
    o4.w = (v.w - mu) * r * gg.w + bb.w;
    ((float4*)(out + (size_t)row * D_))[t] = o4;
}

// ---------------- tiled SGEMM: C = A(MxK) @ W(KxN) [+bias][relu][+resid] ----
// FLAGS: bit0 = +bias, bit1 = relu, bit2 = +resid
#define BM 128
#define BN 64
#define BK 16
#define LDA 132   // padded inner stride for As (multiple of 4 for float4 reads)

template<int FLAGS>
__global__ __launch_bounds__(256) void sgemm(const float* __restrict__ A,
                                             const float* __restrict__ W,
                                             const float* __restrict__ bias,
                                             const float* __restrict__ resid,
                                             float* __restrict__ C,
                                             int K, int N) {
    __shared__ float As[BK][LDA];
    __shared__ float Bs[BK][BN];
    int tid = threadIdx.x;
    int rowStart = blockIdx.y * BM;
    int colStart = blockIdx.x * BN;
    int tr = tid >> 4;          // 0..15  -> 8 rows each
    int tc = tid & 15;          // 0..15  -> 4 cols each
    float acc[8][4];
    #pragma unroll
    for (int m = 0; m < 8; m++)
        #pragma unroll
        for (int n = 0; n < 4; n++) acc[m][n] = 0.0f;

    for (int k0 = 0; k0 < K; k0 += BK) {
        // load A tile (transposed into SMEM)
        #pragma unroll
        for (int i = 0; i < 2; i++) {
            int idx = tid + i * 256;          // 0..511
            int ar = idx >> 2;                // 0..127
            int ak = (idx & 3) * 4;           // 0,4,8,12
            float4 v = *(const float4*)&A[(size_t)(rowStart + ar) * K + k0 + ak];
            As[ak + 0][ar] = v.x;
            As[ak + 1][ar] = v.y;
            As[ak + 2][ar] = v.z;
            As[ak + 3][ar] = v.w;
        }
        // load B tile
        {
            int br = tid >> 4;
            int bc = (tid & 15) * 4;
            *(float4*)&Bs[br][bc] =
                *(const float4*)&W[(size_t)(k0 + br) * N + colStart + bc];
        }
        __syncthreads();
        #pragma unroll
        for (int kk = 0; kk < BK; kk++) {
            float4 a0 = *(const float4*)&As[kk][tr * 8 + 0];
            float4 a1 = *(const float4*)&As[kk][tr * 8 + 4];
            float4 b0 = *(const float4*)&Bs[kk][tc * 4];
            float a[8] = {a0.x, a0.y, a0.z, a0.w, a1.x, a1.y, a1.z, a1.w};
            float bb[4] = {b0.x, b0.y, b0.z, b0.w};
            #pragma unroll
            for (int m = 0; m < 8; m++)
                #pragma unroll
                for (int n = 0; n < 4; n++) acc[m][n] += a[m] * bb[n];
        }
        __syncthreads();
    }
    // epilogue
    #pragma unroll
    for (int m = 0; m < 8; m++) {
        int row = rowStart + tr * 8 + m;
        size_t base = (size_t)row * N + colStart + tc * 4;
        float4 v = make_float4(acc[m][0], acc[m][1], acc[m][2], acc[m][3]);
        if (FLAGS & 1) {
            float4 bb = *(const float4*)&bias[colStart + tc * 4];
            v.x += bb.x; v.y += bb.y; v.z += bb.z; v.w += bb.w;
        }
        if (FLAGS & 2) {
            v.x = fmaxf(v.x, 0.0f); v.y = fmaxf(v.y, 0.0f);
            v.z = fmaxf(v.z, 0.0f); v.w = fmaxf(v.w, 0.0f);
        }
        if (FLAGS & 4) {
            float4 rr = *(const float4*)&resid[base];
            v.x += rr.x; v.y += rr.y; v.z += rr.z; v.w += rr.w;
        }
        *(float4*)&C[base] = v;
    }
}

// ---------------- flash attention (fp32, online softmax) --------------------
// One thread per query row; 64-key tiles staged in SMEM. Prefix mask:
// only keys [0, len) attend; no per-key mask checks needed.
__global__ __launch_bounds__(128) void attn_kernel() {
    int b = blockIdx.z, h = blockIdx.y;
    int r = blockIdx.x * 128 + threadIdx.x;
    int len = g_len[b];

    const float4* qp = (const float4*)(g_q + ((size_t)(b * S_ + r)) * D_ + h * HD_);
    float4 q[16];
    #pragma unroll
    for (int i = 0; i < 16; i++) q[i] = qp[i];

    float4 o[16];
    #pragma unroll
    for (int i = 0; i < 16; i++) o[i] = make_float4(0.f, 0.f, 0.f, 0.f);
    float m = -INFINITY, l = 0.0f;
    const float scale = 0.125f;   // 1/sqrt(64)

    __shared__ float4 k_s[64][16];
    __shared__ float4 v_s[64][16];

    for (int j0 = 0; j0 < len; j0 += 64) {
        int jmax = (len - j0 < 64) ? (len - j0) : 64;
        __syncthreads();
        #pragma unroll
        for (int i = 0; i < 8; i++) {
            int idx = threadIdx.x + i * 128;  // 0..1023
            int row = idx >> 4, c = idx & 15;
            size_t gbase = ((size_t)(b * S_ + j0 + row)) * D_ + h * HD_;
            k_s[row][c] = ((const float4*)(g_k + gbase))[c];
            v_s[row][c] = ((const float4*)(g_v + gbase))[c];
        }
        __syncthreads();

        #pragma unroll 4
        for (int j = 0; j < jmax; j++) {
            float acc = 0.0f;
            #pragma unroll
            for (int i = 0; i < 16; i++) {
                float4 kk = k_s[j][i];
                acc += q[i].x * kk.x + q[i].y * kk.y + q[i].z * kk.z + q[i].w * kk.w;
            }
            float s = acc * scale;
            if (s <= m) {
                float p = expf(s - m);
                l += p;
                #pragma unroll
                for (int i = 0; i < 16; i++) {
                    float4 vv = v_s[j][i];
                    o[i].x += p * vv.x; o[i].y += p * vv.y;
                    o[i].z += p * vv.z; o[i].w += p * vv.w;
                }
            } else {
                float corr = expf(m - s);
                m = s;
                l = l * corr + 1.0f;
                #pragma unroll
                for (int i = 0; i < 16; i++) {
                    float4 vv = v_s[j][i];
                    o[i].x = o[i].x * corr + vv.x; o[i].y = o[i].y * corr + vv.y;
                    o[i].z = o[i].z * corr + vv.z; o[i].w = o[i].w * corr + vv.w;
                }
            }
        }
    }

    float inv = (l > 0.0f) ? (1.0f / l) : 0.0f;   // defensive: never emit NaN
    float4* op = (float4*)(g_h + ((size_t)(b * S_ + r)) * D_ + h * HD_);
    #pragma unroll
    for (int i = 0; i < 16; i++) {
        float4 v = o[i];
        v.x *= inv; v.y *= inv; v.z *= inv; v.w *= inv;
        op[i] = v;
    }
}

// ---------------- launcher ---------------------------------------------------
extern "C" void kernel_launch(void* const* d_in, const int* in_sizes, int n_in,
                              void* d_out, int out_size) {
    const float* x    = (const float*)d_in[0];
    const unsigned int* mask = (const unsigned int*)d_in[1];  // bool -> 4-byte 0/1
    const float* Wq   = (const float*)d_in[2];
    const float* Wk   = (const float*)d_in[3];
    const float* Wv   = (const float*)d_in[4];
    const float* Wo   = (const float*)d_in[5];
    const float* ln1g = (const float*)d_in[6];
    const float* ln1b = (const float*)d_in[7];
    const float* ln2g = (const float*)d_in[8];
    const float* ln2b = (const float*)d_in[9];
    const float* W1   = (const float*)d_in[10];
    const float* b1   = (const float*)d_in[11];
    const float* W2   = (const float*)d_in[12];
    const float* b2   = (const float*)d_in[13];

    float *px, *ph, *pq, *pk, *pv, *pff;
    cudaGetSymbolAddress((void**)&px,  g_x);
    cudaGetSymbolAddress((void**)&ph,  g_h);
    cudaGetSymbolAddress((void**)&pq,  g_q);
    cudaGetSymbolAddress((void**)&pk,  g_k);
    cudaGetSymbolAddress((void**)&pv,  g_v);
    cudaGetSymbolAddress((void**)&pff, g_ff);

    masklen_kernel<<<B_, 256>>>(mask);
    posenc_kernel<<<dim3(S_, B_), 512>>>(x);

    for (int l = 0; l < L_; l++) {
        const float* wq = Wq + (size_t)l * D_ * D_;
        const float* wk = Wk + (size_t)l * D_ * D_;
        const float* wv = Wv + (size_t)l * D_ * D_;
        const float* wo = Wo + (size_t)l * D_ * D_;
        const float* w1 = W1 + (size_t)l * D_ * DFF_;
        const float* w2 = W2 + (size_t)l * DFF_ * D_;

        ln_kernel<<<BS_, 128>>>(px, ln1g + l * D_, ln1b + l * D_, ph);

        dim3 gProj(D_ / BN, BS_ / BM);
        sgemm<0><<<gProj, 256>>>(ph, wq, nullptr, nullptr, pq, D_, D_);
        sgemm<0><<<gProj, 256>>>(ph, wk, nullptr, nullptr, pk, D_, D_);
        sgemm<0><<<gProj, 256>>>(ph, wv, nullptr, nullptr, pv, D_, D_);

        attn_kernel<<<dim3(S_ / 128, H_, B_), 128>>>();

        // x = x + attn_out @ Wo   (resid)
        sgemm<4><<<gProj, 256>>>(ph, wo, nullptr, px, px, D_, D_);

        ln_kernel<<<BS_, 128>>>(px, ln2g + l * D_, ln2b + l * D_, ph);

        // ff = relu(h @ W1 + b1)   (bias + relu)
        sgemm<3><<<dim3(DFF_ / BN, BS_ / BM), 256>>>(ph, w1, b1 + (size_t)l * DFF_,
                                                     nullptr, pff, D_, DFF_);
        // x = x + ff @ W2 + b2     (bias + resid)
        sgemm<5><<<dim3(D_ / BN, BS_ / BM), 256>>>(pff, w2, b2 + (size_t)l * D_,
                                                   px, px, DFF_, D_);
    }

    cudaMemcpyAsync(d_out, px, sizeof(float) * BS_ * D_, cudaMemcpyDeviceToDevice);
}

// round 9
// speedup vs baseline: 1.0024x; 1.0024x over previous
#include <cuda_runtime.h>
#include <math.h>
#include <stdint.h>

#define L_   4
#define D_   512
#define H_   8
#define HD_  64
#define DFF_ 2048
#define B_   8
#define S_   1024
#define BS_  (B_*S_)   // 8192 rows

// ---------------- scratch (device globals; no allocations allowed) ----------
__device__ float g_x [BS_*D_];    // residual stream
__device__ float g_h [BS_*D_];    // layernorm out / attention out
__device__ float g_q [BS_*D_];
__device__ float g_k [BS_*D_];
__device__ float g_v [BS_*D_];
__device__ float g_ff[BS_*DFF_];  // FFN hidden
__device__ int   g_len[B_];       // per-batch valid key count (prefix mask)

// ---------------- mask length extraction (mask is 4-byte 0/1, prefix) -------
__global__ __launch_bounds__(256) void masklen_kernel(const unsigned int* __restrict__ mask) {
    int b = blockIdx.x, t = threadIdx.x;
    int cnt = 0;
    for (int i = t; i < S_; i += 256) cnt += (mask[b * S_ + i] != 0u) ? 1 : 0;
    #pragma unroll
    for (int o = 16; o; o >>= 1) cnt += __shfl_xor_sync(0xffffffffu, cnt, o);
    __shared__ int sh[8];
    if ((t & 31) == 0) sh[t >> 5] = cnt;
    __syncthreads();
    if (t == 0) {
        int s = 0;
        #pragma unroll
        for (int w = 0; w < 8; w++) s += sh[w];
        g_len[b] = s;
    }
}

// ---------------- positional encoding + input copy --------------------------
__global__ __launch_bounds__(512) void posenc_kernel(const float* __restrict__ x) {
    int s = blockIdx.x, b = blockIdx.y, d = threadIdx.x;
    float j = (float)((d < 256) ? d : d - 256);
    float inv = powf(10000.0f, (2.0f * j) / 512.0f);
    float ang = (float)s / inv;
    float pe  = (d < 256) ? sinf(ang) : cosf(ang);
    size_t idx = ((size_t)b * S_ + s) * D_ + d;
    g_x[idx] = x[idx] + pe;
}

// ---------------- layernorm (one block per row, 128 thr x float4) -----------
__global__ __launch_bounds__(128) void ln_kernel(const float* __restrict__ in,
                                                 const float* __restrict__ gw,
                                                 const float* __restrict__ bw,
                                                 float* __restrict__ out) {
    int row = blockIdx.x;
    int t = threadIdx.x;
    const float4* rp = (const float4*)(in + (size_t)row * D_);
    float4 v = rp[t];
    float s  = v.x + v.y + v.z + v.w;
    float sq = v.x*v.x + v.y*v.y + v.z*v.z + v.w*v.w;
    #pragma unroll
    for (int o = 16; o; o >>= 1) {
        s  += __shfl_xor_sync(0xffffffffu, s,  o);
        sq += __shfl_xor_sync(0xffffffffu, sq, o);
    }
    __shared__ float sh[8];
    int wid = t >> 5, lane = t & 31;
    if (lane == 0) { sh[wid] = s; sh[4 + wid] = sq; }
    __syncthreads();
    s  = sh[0] + sh[1] + sh[2] + sh[3];
    sq = sh[4] + sh[5] + sh[6] + sh[7];
    float mu  = s * (1.0f / D_);
    float var = sq * (1.0f / D_) - mu * mu;
    float r   = rsqrtf(var + 1e-3f);
    float4 gg = ((const float4*)gw)[t];
    float4 bb = ((const float4*)bw)[t];
    float4 o4;
    o4.x = (v.x - mu) * r * gg.x + bb.x;
    o4.y = (v.y - mu) * r * gg.y + bb.y;
    o4.z = (v.z - mu) * r * gg.z + bb.z;
    o4.w = (v.w - mu) * r * gg.w + bb.w;
    ((float4*)(out + (size_t)row * D_))[t] = o4;
}

// ============================================================================
// Tensor-core GEMM: C = A(MxK) @ W(KxN) [+bias][relu][+resid]
// 3xTF32 split for ~fp32 accuracy on the tensor pipe.
// BM=128, BN=64, BK=16; 256 threads = 8 warps; warp tile 32x32 (2x4 m16n8k8).
// ============================================================================
#define BM 128
#define BN 64
#define BK 16
#define LDA2 136   // stride mod 32 == 8 -> conflict-free fragment LDS
#define LDB2 72

__device__ __forceinline__ uint32_t f2tf32(float x) {
    uint32_t r;
    asm("cvt.rna.tf32.f32 %0, %1;" : "=r"(r) : "f"(x));
    return r;
}

__device__ __forceinline__ void mma_tf32(float c[4], const uint32_t a[4], const uint32_t b[2]) {
    asm volatile(
        "mma.sync.aligned.m16n8k8.row.col.f32.tf32.tf32.f32 "
        "{%0,%1,%2,%3}, {%4,%5,%6,%7}, {%8,%9}, {%0,%1,%2,%3};\n"
        : "+f"(c[0]), "+f"(c[1]), "+f"(c[2]), "+f"(c[3])
        : "r"(a[0]), "r"(a[1]), "r"(a[2]), "r"(a[3]),
          "r"(b[0]), "r"(b[1]));
}

// FLAGS: bit0 = +bias, bit1 = relu, bit2 = +resid
template<int FLAGS>
__global__ __launch_bounds__(256, 2) void sgemm(const float* __restrict__ A,
                                                const float* __restrict__ W,
                                                const float* __restrict__ bias,
                                                const float* __restrict__ resid,
                                                float* __restrict__ C,
                                                int K, int N) {
    __shared__ uint32_t As_hi[BK][LDA2];
    __shared__ uint32_t As_lo[BK][LDA2];
    __shared__ uint32_t Bs_hi[BK][LDB2];
    __shared__ uint32_t Bs_lo[BK][LDB2];

    int tid  = threadIdx.x;
    int warp = tid >> 5;
    int lane = tid & 31;
    int warpM = warp & 3;      // 0..3 (M tiles of 32)
    int warpN = warp >> 2;     // 0..1 (N tiles of 32)
    int gid = lane >> 2;       // 0..7
    int tig = lane & 3;        // 0..3
    int rowStart = blockIdx.y * BM;
    int colStart = blockIdx.x * BN;

    float acc[2][4][4];
    #pragma unroll
    for (int mt = 0; mt < 2; mt++)
        #pragma unroll
        for (int nt = 0; nt < 4; nt++)
            #pragma unroll
            for (int r = 0; r < 4; r++) acc[mt][nt][r] = 0.0f;

    float4 pa[2];   // A prefetch regs
    float4 pb;      // B prefetch regs

    // gmem load helper indices
    int a_r0 = (tid) >> 2;              // 0..63   (i=0)
    int a_k0 = (tid & 3) * 4;
    int b_r  = tid >> 4;                // 0..15
    int b_c  = (tid & 15) * 4;

    // ---- prologue: load tile k0=0 ----
    {
        pa[0] = *(const float4*)&A[(size_t)(rowStart + a_r0) * K + a_k0];
        pa[1] = *(const float4*)&A[(size_t)(rowStart + a_r0 + 64) * K + a_k0];
        pb    = *(const float4*)&W[(size_t)b_r * N + colStart + b_c];
    }
    // store prologue tile
    {
        #pragma unroll
        for (int i = 0; i < 2; i++) {
            int ar = a_r0 + i * 64;
            float v[4] = {pa[i].x, pa[i].y, pa[i].z, pa[i].w};
            #pragma unroll
            for (int j = 0; j < 4; j++) {
                uint32_t hi = f2tf32(v[j]);
                float lo = v[j] - __uint_as_float(hi);
                As_hi[a_k0 + j][ar] = hi;
                As_lo[a_k0 + j][ar] = f2tf32(lo);
            }
        }
        float v[4] = {pb.x, pb.y, pb.z, pb.w};
        uint32_t h4[4], l4[4];
        #pragma unroll
        for (int j = 0; j < 4; j++) {
            h4[j] = f2tf32(v[j]);
            l4[j] = f2tf32(v[j] - __uint_as_float(h4[j]));
        }
        *(uint4*)&Bs_hi[b_r][b_c] = make_uint4(h4[0], h4[1], h4[2], h4[3]);
        *(uint4*)&Bs_lo[b_r][b_c] = make_uint4(l4[0], l4[1], l4[2], l4[3]);
    }
    __syncthreads();

    int m0 = warpM * 32;
    int n0 = warpN * 32;

    for (int k0 = BK; k0 <= K; k0 += BK) {
        bool more = (k0 < K);
        if (more) {
            pa[0] = *(const float4*)&A[(size_t)(rowStart + a_r0) * K + k0 + a_k0];
            pa[1] = *(const float4*)&A[(size_t)(rowStart + a_r0 + 64) * K + k0 + a_k0];
            pb    = *(const float4*)&W[(size_t)(k0 + b_r) * N + colStart + b_c];
        }

        // ---- compute on current SMEM tile ----
        #pragma unroll
        for (int ks = 0; ks < 2; ks++) {
            int kb = ks * 8;
            uint32_t ah[2][4], al[2][4], bh[4][2], bl[4][2];
            #pragma unroll
            for (int mt = 0; mt < 2; mt++) {
                int mm = m0 + mt * 16;
                ah[mt][0] = As_hi[kb + tig    ][mm + gid    ];
                ah[mt][1] = As_hi[kb + tig    ][mm + gid + 8];
                ah[mt][2] = As_hi[kb + tig + 4][mm + gid    ];
                ah[mt][3] = As_hi[kb + tig + 4][mm + gid + 8];
                al[mt][0] = As_lo[kb + tig    ][mm + gid    ];
                al[mt][1] = As_lo[kb + tig    ][mm + gid + 8];
                al[mt][2] = As_lo[kb + tig + 4][mm + gid    ];
                al[mt][3] = As_lo[kb + tig + 4][mm + gid + 8];
            }
            #pragma unroll
            for (int nt = 0; nt < 4; nt++) {
                int nn = n0 + nt * 8;
                bh[nt][0] = Bs_hi[kb + tig    ][nn + gid];
                bh[nt][1] = Bs_hi[kb + tig + 4][nn + gid];
                bl[nt][0] = Bs_lo[kb + tig    ][nn + gid];
                bl[nt][1] = Bs_lo[kb + tig + 4][nn + gid];
            }
            #pragma unroll
            for (int mt = 0; mt < 2; mt++)
                #pragma unroll
                for (int nt = 0; nt < 4; nt++) {
                    mma_tf32(acc[mt][nt], ah[mt], bh[nt]);
                    mma_tf32(acc[mt][nt], ah[mt], bl[nt]);
                    mma_tf32(acc[mt][nt], al[mt], bh[nt]);
                }
        }
        __syncthreads();

        if (more) {
            #pragma unroll
            for (int i = 0; i < 2; i++) {
                int ar = a_r0 + i * 64;
                float v[4] = {pa[i].x, pa[i].y, pa[i].z, pa[i].w};
                #pragma unroll
                for (int j = 0; j < 4; j++) {
                    uint32_t hi = f2tf32(v[j]);
                    float lo = v[j] - __uint_as_float(hi);
                    As_hi[a_k0 + j][ar] = hi;
                    As_lo[a_k0 + j][ar] = f2tf32(lo);
                }
            }
            float v[4] = {pb.x, pb.y, pb.z, pb.w};
            uint32_t h4[4], l4[4];
            #pragma unroll
            for (int j = 0; j < 4; j++) {
                h4[j] = f2tf32(v[j]);
                l4[j] = f2tf32(v[j] - __uint_as_float(h4[j]));
            }
            *(uint4*)&Bs_hi[b_r][b_c] = make_uint4(h4[0], h4[1], h4[2], h4[3]);
            *(uint4*)&Bs_lo[b_r][b_c] = make_uint4(l4[0], l4[1], l4[2], l4[3]);
            __syncthreads();
        }
    }

    // ---- epilogue ----
    #pragma unroll
    for (int mt = 0; mt < 2; mt++) {
        #pragma unroll
        for (int half = 0; half < 2; half++) {
            int row = rowStart + m0 + mt * 16 + gid + half * 8;
            #pragma unroll
            for (int nt = 0; nt < 4; nt++) {
                int col = colStart + n0 + nt * 8 + tig * 2;
                size_t base = (size_t)row * N + col;
                float2 v;
                v.x = acc[mt][nt][half * 2 + 0];
                v.y = acc[mt][nt][half * 2 + 1];
                if (FLAGS & 1) {
                    float2 bb = *(const float2*)&bias[col];
                    v.x += bb.x; v.y += bb.y;
                }
                if (FLAGS & 2) {
                    v.x = fmaxf(v.x, 0.0f); v.y = fmaxf(v.y, 0.0f);
                }
                if (FLAGS & 4) {
                    float2 rr = *(const float2*)&resid[base];
                    v.x += rr.x; v.y += rr.y;
                }
                *(float2*)&C[base] = v;
            }
        }
    }
}

// ---------------- flash attention (fp32, online softmax) --------------------
__global__ __launch_bounds__(128) void attn_kernel() {
    int b = blockIdx.z, h = blockIdx.y;
    int r = blockIdx.x * 128 + threadIdx.x;
    int len = g_len[b];

    const float4* qp = (const float4*)(g_q + ((size_t)(b * S_ + r)) * D_ + h * HD_);
    float4 q[16];
    #pragma unroll
    for (int i = 0; i < 16; i++) q[i] = qp[i];

    float4 o[16];
    #pragma unroll
    for (int i = 0; i < 16; i++) o[i] = make_float4(0.f, 0.f, 0.f, 0.f);
    float m = -INFINITY, l = 0.0f;
    const float scale = 0.125f;   // 1/sqrt(64)

    __shared__ float4 k_s[64][16];
    __shared__ float4 v_s[64][16];

    for (int j0 = 0; j0 < len; j0 += 64) {
        int jmax = (len - j0 < 64) ? (len - j0) : 64;
        __syncthreads();
        #pragma unroll
        for (int i = 0; i < 8; i++) {
            int idx = threadIdx.x + i * 128;  // 0..1023
            int row = idx >> 4, c = idx & 15;
            size_t gbase = ((size_t)(b * S_ + j0 + row)) * D_ + h * HD_;
            k_s[row][c] = ((const float4*)(g_k + gbase))[c];
            v_s[row][c] = ((const float4*)(g_v + gbase))[c];
        }
        __syncthreads();

        #pragma unroll 4
        for (int j = 0; j < jmax; j++) {
            float acc = 0.0f;
            #pragma unroll
            for (int i = 0; i < 16; i++) {
                float4 kk = k_s[j][i];
                acc += q[i].x * kk.x + q[i].y * kk.y + q[i].z * kk.z + q[i].w * kk.w;
            }
            float s = acc * scale;
            if (s <= m) {
                float p = expf(s - m);
                l += p;
                #pragma unroll
                for (int i = 0; i < 16; i++) {
                    float4 vv = v_s[j][i];
                    o[i].x += p * vv.x; o[i].y += p * vv.y;
                    o[i].z += p * vv.z; o[i].w += p * vv.w;
                }
            } else {
                float corr = expf(m - s);
                m = s;
                l = l * corr + 1.0f;
                #pragma unroll
                for (int i = 0; i < 16; i++) {
                    float4 vv = v_s[j][i];
                    o[i].x = o[i].x * corr + vv.x; o[i].y = o[i].y * corr + vv.y;
                    o[i].z = o[i].z * corr + vv.z; o[i].w = o[i].w * corr + vv.w;
                }
            }
        }
    }

    float inv = (l > 0.0f) ? (1.0f / l) : 0.0f;   // defensive: never emit NaN
    float4* op = (float4*)(g_h + ((size_t)(b * S_ + r)) * D_ + h * HD_);
    #pragma unroll
    for (int i = 0; i < 16; i++) {
        float4 v = o[i];
        v.x *= inv; v.y *= inv; v.z *= inv; v.w *= inv;
        op[i] = v;
    }
}

// ---------------- launcher ---------------------------------------------------
extern "C" void kernel_launch(void* const* d_in, const int* in_sizes, int n_in,
                              void* d_out, int out_size) {
    const float* x    = (const float*)d_in[0];
    const unsigned int* mask = (const unsigned int*)d_in[1];  // bool -> 4-byte 0/1
    const float* Wq   = (const float*)d_in[2];
    const float* Wk   = (const float*)d_in[3];
    const float* Wv   = (const float*)d_in[4];
    const float* Wo   = (const float*)d_in[5];
    const float* ln1g = (const float*)d_in[6];
    const float* ln1b = (const float*)d_in[7];
    const float* ln2g = (const float*)d_in[8];
    const float* ln2b = (const float*)d_in[9];
    const float* W1   = (const float*)d_in[10];
    const float* b1   = (const float*)d_in[11];
    const float* W2   = (const float*)d_in[12];
    const float* b2   = (const float*)d_in[13];

    float *px, *ph, *pq, *pk, *pv, *pff;
    cudaGetSymbolAddress((void**)&px,  g_x);
    cudaGetSymbolAddress((void**)&ph,  g_h);
    cudaGetSymbolAddress((void**)&pq,  g_q);
    cudaGetSymbolAddress((void**)&pk,  g_k);
    cudaGetSymbolAddress((void**)&pv,  g_v);
    cudaGetSymbolAddress((void**)&pff, g_ff);

    masklen_kernel<<<B_, 256>>>(mask);
    posenc_kernel<<<dim3(S_, B_), 512>>>(x);

    for (int l = 0; l < L_; l++) {
        const float* wq = Wq + (size_t)l * D_ * D_;
        const float* wk = Wk + (size_t)l * D_ * D_;
        const float* wv = Wv + (size_t)l * D_ * D_;
        const float* wo = Wo + (size_t)l * D_ * D_;
        const float* w1 = W1 + (size_t)l * D_ * DFF_;
        const float* w2 = W2 + (size_t)l * DFF_ * D_;

        ln_kernel<<<BS_, 128>>>(px, ln1g + l * D_, ln1b + l * D_, ph);

        dim3 gProj(D_ / BN, BS_ / BM);
        sgemm<0><<<gProj, 256>>>(ph, wq, nullptr, nullptr, pq, D_, D_);
        sgemm<0><<<gProj, 256>>>(ph, wk, nullptr, nullptr, pk, D_, D_);
        sgemm<0><<<gProj, 256>>>(ph, wv, nullptr, nullptr, pv, D_, D_);

        attn_kernel<<<dim3(S_ / 128, H_, B_), 128>>>();

        // x = x + attn_out @ Wo   (resid)
        sgemm<4><<<gProj, 256>>>(ph, wo, nullptr, px, px, D_, D_);

        ln_kernel<<<BS_, 128>>>(px, ln2g + l * D_, ln2b + l * D_, ph);

        // ff = relu(h @ W1 + b1)   (bias + relu)
        sgemm<3><<<dim3(DFF_ / BN, BS_ / BM), 256>>>(ph, w1, b1 + (size_t)l * DFF_,
                                                     nullptr, pff, D_, DFF_);
        // x = x + ff @ W2 + b2     (bias + resid)
        sgemm<5><<<dim3(D_ / BN, BS_ / BM), 256>>>(pff, w2, b2 + (size_t)l * D_,
                                                   px, px, DFF_, D_);
    }

    cudaMemcpyAsync(d_out, px, sizeof(float) * BS_ * D_, cudaMemcpyDeviceToDevice);
}